// round 14
// baseline (speedup 1.0000x reference)
#include <cuda_runtime.h>
#include <cuda_fp16.h>
#include <math.h>
#include <stdint.h>

#define BATCH 8
#define SEQ   2048
#define NBL   (BATCH*SEQ)          // 16384
#define DM    512
#define DIN   1024
#define NH    16
#define HD    64
#define DS    64
#define CONVD 1152
#define DPROJ 2192
#define DFF   2048
#define EPSR  1e-6f

// ===================== scratch (static device; no cudaMalloc) =====================
static __device__ float g_xraw[(size_t)NBL*CONVD];
static __device__ float g_xbc[(size_t)NBL*CONVD];
static __device__ float g_yf[(size_t)NBL*DIN];
static __device__ float g_yb[(size_t)NBL*DIN];
// fp16 activations
static __device__ __half g_u[(size_t)NBL*DM];
static __device__ __half g_y2[(size_t)NBL*DIN];
static __device__ __half g_h[(size_t)NBL*DM];
static __device__ __half g_ff[(size_t)NBL*DFF];
// fp16 transposed weights [N,K]
static __device__ __half g_wi[(size_t)DPROJ*DM];
static __device__ __half g_wo[(size_t)DM*DIN];
static __device__ __half g_w1[(size_t)DFF*DM];
static __device__ __half g_w2[(size_t)DM*DFF];

// ===================== helpers =====================
__device__ __forceinline__ uint32_t smem_to_u32(const void* smem_ptr) {
    uint32_t addr;
    asm("{ .reg .u64 tmp; cvta.to.shared.u64 tmp, %1; cvt.u32.u64 %0, tmp; }"
        : "=r"(addr) : "l"(smem_ptr));
    return addr;
}
__device__ __forceinline__ void cp_async16(uint32_t dst, const void* src, uint32_t bytes){
    asm volatile("cp.async.cg.shared.global [%0], [%1], 16, %2;"
                 :: "r"(dst), "l"(src), "r"(bytes));
}
#define CP_COMMIT() asm volatile("cp.async.commit_group;")
#define CP_WAIT1()  asm volatile("cp.async.wait_group 1;")
#define CP_WAIT0()  asm volatile("cp.async.wait_group 0;")

__device__ __forceinline__ void ldm_x4(uint32_t addr, uint32_t& r0, uint32_t& r1,
                                       uint32_t& r2, uint32_t& r3){
    asm volatile("ldmatrix.sync.aligned.m8n8.x4.shared.b16 {%0,%1,%2,%3}, [%4];"
                 : "=r"(r0), "=r"(r1), "=r"(r2), "=r"(r3) : "r"(addr));
}
__device__ __forceinline__ void mma16816(float* c, const uint32_t* a, const uint32_t* b){
    asm volatile(
        "mma.sync.aligned.m16n8k16.row.col.f32.f16.f16.f32 "
        "{%0,%1,%2,%3}, {%4,%5,%6,%7}, {%8,%9}, {%0,%1,%2,%3};"
        : "+f"(c[0]), "+f"(c[1]), "+f"(c[2]), "+f"(c[3])
        : "r"(a[0]), "r"(a[1]), "r"(a[2]), "r"(a[3]), "r"(b[0]), "r"(b[1]));
}

__device__ __forceinline__ float siluf(float x){ return x / (1.f + expf(-x)); }
__device__ __forceinline__ float geluf(float x){
    float x3 = x*x*x;
    return 0.5f*x*(1.f + tanhf(0.7978845608028654f*(x + 0.044715f*x3)));
}
__device__ __forceinline__ float softplusf(float x){
    return fmaxf(x, 0.f) + log1pf(expf(-fabsf(x)));
}

// ===================== weight transpose: W[K,N] fp32 -> T[N,K] fp16 ==============
__global__ void wconv_kernel(const float* __restrict__ W,
                             __half* __restrict__ T, int K, int N){
    __shared__ float tile[32][33];
    int n0 = blockIdx.x*32, k0 = blockIdx.y*32;
    int tx = threadIdx.x, ty = threadIdx.y;
    #pragma unroll
    for (int i=0;i<32;i+=8){
        int k = k0+ty+i, n = n0+tx;
        tile[ty+i][tx] = (n < N) ? W[(size_t)k*N + n] : 0.f;
    }
    __syncthreads();
    #pragma unroll
    for (int i=0;i<32;i+=8){
        int n = n0+ty+i, k = k0+tx;
        if (n < N) T[(size_t)n*K + k] = __float2half(tile[tx][ty+i]);
    }
}

// ===================== fp16 HMMA GEMM, BK=64 (frozen) ============================
#define BK 64
#define LDSB 144
#define MAT_ELEMS (128*72)
#define STAGE_BYTES (2*MAT_ELEMS*2)
#define GSMEM_BYTES (3*STAGE_BYTES)

template<int MODE>
__global__ void __launch_bounds__(256,2)
mma_gemm(const __half* __restrict__ A, const __half* __restrict__ B,
         int N, int K,
         float* __restrict__ C, const float* __restrict__ bias,
         const float* __restrict__ res, __half* __restrict__ Oh,
         float* __restrict__ z_out, float* __restrict__ xraw,
         float* __restrict__ dt_out, const float* __restrict__ dtb)
{
    extern __shared__ __half smem[];
    const uint32_t sb = smem_to_u32(smem);
    const int tid = threadIdx.x;
    const int lane = tid & 31, wid = tid >> 5;
    const int row0 = blockIdx.y * 128;
    const int n0   = blockIdx.x * 128;
    const int wm0 = (wid & 3) * 32;
    const int wn0 = (wid >> 2) * 64;

    const uint32_t aoff = (uint32_t)((lane & 15) * LDSB + (lane >> 4) * 16);
    const uint32_t boff = (uint32_t)(((lane & 7) + ((lane & 16) >> 1)) * LDSB + (lane & 8) * 2);

    float acc[2][8][4];
    #pragma unroll
    for (int i=0;i<2;i++)
        #pragma unroll
        for (int j=0;j<8;j++)
            #pragma unroll
            for (int q=0;q<4;q++) acc[i][j][q]=0.f;

    const int nch = K / BK;

    auto issue = [&](int ch){
        const int k0 = ch * BK;
        uint32_t base = sb + (uint32_t)((ch % 3) * STAGE_BYTES);
        #pragma unroll
        for (int i=0;i<4;i++){
            int id = tid + i*256;
            int r = id >> 3, c8e = (id & 7) * 8;
            size_t g = (size_t)(row0 + r) * K + k0 + c8e;
            uint32_t so = (uint32_t)(r * LDSB + c8e * 2);
            cp_async16(base + so, A + g, 16);
        }
        #pragma unroll
        for (int i=0;i<4;i++){
            int id = tid + i*256;
            int r = id >> 3, c8e = (id & 7) * 8;
            int n = n0 + r;
            int valid = (n < N);
            size_t g = (size_t)(valid ? n : 0) * K + k0 + c8e;
            uint32_t so = (uint32_t)(r * LDSB + c8e * 2);
            cp_async16(base + (uint32_t)MAT_ELEMS*2 + so, B + g, valid ? 16u : 0u);
        }
        CP_COMMIT();
    };

    issue(0); if (nch > 1) issue(1);
    for (int ch = 0; ch < nch; ch++){
        if (ch + 1 < nch) CP_WAIT1(); else CP_WAIT0();
        __syncthreads();
        if (ch + 2 < nch) issue(ch + 2);

        const uint32_t base = sb + (uint32_t)((ch % 3) * STAGE_BYTES);
        const uint32_t bA = base;
        const uint32_t bB = base + (uint32_t)MAT_ELEMS*2;

        #pragma unroll
        for (int ks = 0; ks < BK; ks += 16){
            uint32_t a[2][4], b[8][2];
            #pragma unroll
            for (int mt = 0; mt < 2; mt++){
                uint32_t ao = (uint32_t)((wm0 + mt*16) * LDSB + ks*2) + aoff;
                ldm_x4(bA + ao, a[mt][0], a[mt][1], a[mt][2], a[mt][3]);
            }
            #pragma unroll
            for (int p = 0; p < 4; p++){
                uint32_t bo = (uint32_t)((wn0 + p*16) * LDSB + ks*2) + boff;
                ldm_x4(bB + bo, b[2*p][0], b[2*p][1], b[2*p+1][0], b[2*p+1][1]);
            }
            #pragma unroll
            for (int mt = 0; mt < 2; mt++)
                #pragma unroll
                for (int nt = 0; nt < 8; nt++)
                    mma16816(acc[mt][nt], a[mt], b[nt]);
        }
        __syncthreads();
    }

    const int rb = row0 + wm0 + (lane >> 2);
    const int cb = n0 + wn0 + (lane & 3) * 2;
    #pragma unroll
    for (int mt = 0; mt < 2; mt++){
        #pragma unroll
        for (int nt = 0; nt < 8; nt++){
            int c = cb + nt*8;
            if (c >= N) continue;
            #pragma unroll
            for (int half = 0; half < 2; half++){
                int r = rb + mt*16 + half*8;
                float v0 = acc[mt][nt][half*2+0];
                float v1 = acc[mt][nt][half*2+1];
                size_t o = (size_t)r*N + c;
                if (MODE == 0){
                    *(float2*)(C + o) = make_float2(v0, v1);
                } else if (MODE == 1){
                    v0 = geluf(v0 + bias[c]);
                    v1 = geluf(v1 + bias[c+1]);
                    __half2 hp; hp.x = __float2half(v0); hp.y = __float2half(v1);
                    *(__half2*)(Oh + o) = hp;
                } else if (MODE == 2){
                    float2 rv = *(const float2*)(res + o);
                    *(float2*)(C + o) = make_float2(v0 + bias[c]   + 2.f*rv.x,
                                                    v1 + bias[c+1] + 2.f*rv.y);
                } else {
                    if (c < DIN){
                        *(float2*)(z_out + (size_t)r*DIN + c) = make_float2(v0, v1);
                    } else if (c < DIN + CONVD){
                        *(float2*)(xraw + (size_t)r*CONVD + (c - DIN)) = make_float2(v0, v1);
                    } else {
                        int hh2 = c - (DIN + CONVD);
                        dt_out[(size_t)r*NH + hh2]     = softplusf(v0 + dtb[hh2]);
                        dt_out[(size_t)r*NH + hh2 + 1] = softplusf(v1 + dtb[hh2+1]);
                    }
                }
            }
        }
    }
}

// ===================== u = rmsnorm(x*mask) -> fp16 =====================
__global__ void __launch_bounds__(128) prenorm_kernel(const float* __restrict__ x,
                                                      const float* __restrict__ mask,
                                                      __half* __restrict__ u){
    int row = blockIdx.x; int t = threadIdx.x;
    float mk = mask[row];
    float4 a = ((const float4*)(x + (size_t)row*DM))[t];
    a.x*=mk; a.y*=mk; a.z*=mk; a.w*=mk;
    float ss = a.x*a.x + a.y*a.y + a.z*a.z + a.w*a.w;
    __shared__ float sh[4];
    #pragma unroll
    for (int o=16;o;o>>=1) ss += __shfl_xor_sync(0xffffffffu, ss, o);
    if ((t&31)==0) sh[t>>5] = ss;
    __syncthreads();
    float inv = rsqrtf((sh[0]+sh[1]+sh[2]+sh[3])*(1.f/DM) + EPSR);
    __half2 p0, p1;
    p0.x = __float2half(a.x*inv); p0.y = __float2half(a.y*inv);
    p1.x = __float2half(a.z*inv); p1.y = __float2half(a.w*inv);
    size_t o = (size_t)row*DM + t*4;
    *(__half2*)(u+o)   = p0;
    *(__half2*)(u+o+2) = p1;
}

// ===================== conv + silu + mask, float4 (frozen) =======================
__global__ void conv_kernel(const float* __restrict__ cw, const float* __restrict__ cb,
                            const float* __restrict__ mask){
    long idx = (long)blockIdx.x*blockDim.x + threadIdx.x;
    if (idx >= (long)NBL*(CONVD/4)) return;
    int c4 = (int)(idx % (CONVD/4));
    long bl = idx / (CONVD/4);
    int l = (int)(bl % SEQ);
    int c = c4 * 4;
    float4 w0 = *(const float4*)(cw + (size_t)c*4);
    float4 w1 = *(const float4*)(cw + (size_t)(c+1)*4);
    float4 w2 = *(const float4*)(cw + (size_t)(c+2)*4);
    float4 w3 = *(const float4*)(cw + (size_t)(c+3)*4);
    float4 acc = *(const float4*)(cb + c);
    float4 xt[4];
    #pragma unroll
    for (int i=0;i<4;i++){
        int ls = l + i - 3;
        if (ls >= 0) xt[i] = *(const float4*)(g_xraw + (size_t)(bl + (i-3))*CONVD + c);
        else         xt[i] = make_float4(0.f,0.f,0.f,0.f);
    }
    acc.x += xt[0].x*w0.x + xt[1].x*w0.y + xt[2].x*w0.z + xt[3].x*w0.w;
    acc.y += xt[0].y*w1.x + xt[1].y*w1.y + xt[2].y*w1.z + xt[3].y*w1.w;
    acc.z += xt[0].z*w2.x + xt[1].z*w2.y + xt[2].z*w2.z + xt[3].z*w2.w;
    acc.w += xt[0].w*w3.x + xt[1].w*w3.y + xt[2].w*w3.z + xt[3].w*w3.w;
    float mk = mask[bl];
    float4 o4;
    o4.x = siluf(acc.x)*mk; o4.y = siluf(acc.y)*mk;
    o4.z = siluf(acc.z)*mk; o4.w = siluf(acc.w)*mk;
    *(float4*)(g_xbc + (size_t)bl*CONVD + c) = o4;
}

// ===================== bidirectional SSM scan (4-way state split) ================
// grid (2, NH, BATCH), 256 threads. Thread group (4p..4p+3) owns state row p;
// each thread handles 16 of 64 state cols (4 float4). Same total FMA count as
// the 2-way version but 2x warps -> 2x issue capacity.
#define CT 32
__global__ void __launch_bounds__(256) scan_kernel(const float* __restrict__ dtb,
                                                   const float* __restrict__ A_log,
                                                   const float* __restrict__ Dv,
                                                   float* __restrict__ yf,
                                                   float* __restrict__ yb){
    const int dir = blockIdx.x;
    const int h   = blockIdx.y;
    const int b   = blockIdx.z;
    const int tid = threadIdx.x;
    const int p = tid >> 2;
    const int q = tid & 3;
    const int nbase = q << 4;     // 0,16,32,48
    const float Ah = -expf(A_log[h]);
    const float Dh = Dv[h];
    float st[16];
    #pragma unroll
    for (int j=0;j<16;j++) st[j]=0.f;
    __shared__ float Bs[CT][64];
    __shared__ float Cs[CT][64];
    __shared__ float Xs[CT][64];
    __shared__ float Ts[CT];
    __shared__ float dAs[CT];
    const size_t base = (size_t)b*SEQ;
    float* yout = dir ? yb : yf;
    for (int t0=0; t0<SEQ; t0+=CT){
        for (int idx = tid; idx < CT*16; idx += 256){
            int tt = idx >> 4, qq = idx & 15;
            int t = dir ? (SEQ-1-(t0+tt)) : (t0+tt);
            const float4* src = (const float4*)(g_xbc + (base + t)*(size_t)CONVD);
            ((float4*)&Bs[tt][0])[qq] = src[(DIN>>2) + qq];
            ((float4*)&Cs[tt][0])[qq] = src[((DIN+DS)>>2) + qq];
            ((float4*)&Xs[tt][0])[qq] = src[((h*HD)>>2) + qq];
        }
        if (tid < CT){
            int t = dir ? (SEQ-1-(t0+tid)) : (t0+tid);
            float dtv = dtb[(base + t)*NH + h];
            Ts[tid] = dtv;
            dAs[tid] = __expf(dtv*Ah);
        }
        __syncthreads();
        for (int tt=0; tt<CT; tt++){
            float dtv = Ts[tt];
            float dA  = dAs[tt];
            float xv  = Xs[tt][p];
            float dtx = dtv * xv;
            const float4* Bp = (const float4*)(&Bs[tt][nbase]);
            const float4* Cp = (const float4*)(&Cs[tt][nbase]);
            float y0=0.f, y1=0.f, y2v=0.f, y3=0.f;
            #pragma unroll
            for (int j=0;j<4;j++){
                float4 bv = Bp[j];
                float4 cv = Cp[j];
                st[4*j+0] = fmaf(dA, st[4*j+0], dtx*bv.x); y0  = fmaf(st[4*j+0], cv.x, y0);
                st[4*j+1] = fmaf(dA, st[4*j+1], dtx*bv.y); y1  = fmaf(st[4*j+1], cv.y, y1);
                st[4*j+2] = fmaf(dA, st[4*j+2], dtx*bv.z); y2v = fmaf(st[4*j+2], cv.z, y2v);
                st[4*j+3] = fmaf(dA, st[4*j+3], dtx*bv.w); y3  = fmaf(st[4*j+3], cv.w, y3);
            }
            float y = (y0+y1) + (y2v+y3);
            y += __shfl_xor_sync(0xffffffffu, y, 1);
            y += __shfl_xor_sync(0xffffffffu, y, 2);
            if (q == 0){
                int t = dir ? (SEQ-1-(t0+tt)) : (t0+tt);
                float yv = y;
                if (dir==0) yv = fmaf(Dh, xv, yv);
                yout[(base + t)*(size_t)DIN + h*HD + p] = yv;
            }
        }
        __syncthreads();
    }
}

// ===================== y2 = rmsnorm((yf+yb) * silu(z)) * norm_w -> fp16 ==========
__global__ void __launch_bounds__(256) gatednorm_kernel(const float* __restrict__ z,
                                                        const float* __restrict__ w,
                                                        __half* __restrict__ y2){
    int row = blockIdx.x; int t = threadIdx.x;
    float4 ya = ((const float4*)(g_yf + (size_t)row*DIN))[t];
    float4 ybv = ((const float4*)(g_yb + (size_t)row*DIN))[t];
    float4 zv = ((const float4*)(z    + (size_t)row*DIN))[t];
    float4 v;
    v.x = (ya.x + ybv.x) * siluf(zv.x);
    v.y = (ya.y + ybv.y) * siluf(zv.y);
    v.z = (ya.z + ybv.z) * siluf(zv.z);
    v.w = (ya.w + ybv.w) * siluf(zv.w);
    float ss = v.x*v.x + v.y*v.y + v.z*v.z + v.w*v.w;
    __shared__ float sh[8];
    #pragma unroll
    for (int o=16;o;o>>=1) ss += __shfl_xor_sync(0xffffffffu, ss, o);
    if ((t&31)==0) sh[t>>5] = ss;
    __syncthreads();
    float tot = sh[0]+sh[1]+sh[2]+sh[3]+sh[4]+sh[5]+sh[6]+sh[7];
    float inv = rsqrtf(tot*(1.f/DIN) + EPSR);
    float4 wv = ((const float4*)w)[t];
    __half2 p0, p1;
    p0.x = __float2half(v.x*inv*wv.x); p0.y = __float2half(v.y*inv*wv.y);
    p1.x = __float2half(v.z*inv*wv.z); p1.y = __float2half(v.w*inv*wv.w);
    size_t o = (size_t)row*DIN + t*4;
    *(__half2*)(y2+o)   = p0;
    *(__half2*)(y2+o+2) = p1;
}

// ===================== h = rmsnorm(2*m) -> fp16 =====================
__global__ void __launch_bounds__(128) postnorm_kernel(const float* __restrict__ m,
                                                       __half* __restrict__ hbuf){
    int row = blockIdx.x; int t = threadIdx.x;
    float4 mv = ((const float4*)(m + (size_t)row*DM))[t];
    float4 v = make_float4(2.f*mv.x, 2.f*mv.y, 2.f*mv.z, 2.f*mv.w);
    float ss = v.x*v.x + v.y*v.y + v.z*v.z + v.w*v.w;
    __shared__ float sh[4];
    #pragma unroll
    for (int o=16;o;o>>=1) ss += __shfl_xor_sync(0xffffffffu, ss, o);
    if ((t&31)==0) sh[t>>5] = ss;
    __syncthreads();
    float inv = rsqrtf((sh[0]+sh[1]+sh[2]+sh[3])*(1.f/DM) + EPSR);
    __half2 p0, p1;
    p0.x = __float2half(v.x*inv); p0.y = __float2half(v.y*inv);
    p1.x = __float2half(v.z*inv); p1.y = __float2half(v.w*inv);
    size_t o = (size_t)row*DM + t*4;
    *(__half2*)(hbuf+o)   = p0;
    *(__half2*)(hbuf+o+2) = p1;
}

extern "C" void kernel_launch(void* const* d_in, const int* in_sizes, int n_in,
                              void* d_out, int out_size){
    const float* x      = (const float*)d_in[0];
    const float* mask   = (const float*)d_in[1];
    const float* W_in   = (const float*)d_in[2];
    const float* conv_w = (const float*)d_in[3];
    const float* conv_b = (const float*)d_in[4];
    const float* dt_bias= (const float*)d_in[5];
    const float* A_log  = (const float*)d_in[6];
    const float* Dv     = (const float*)d_in[7];
    const float* norm_w = (const float*)d_in[8];
    const float* W_out  = (const float*)d_in[9];
    const float* W1     = (const float*)d_in[10];
    const float* b1     = (const float*)d_in[11];
    const float* W2     = (const float*)d_in[12];
    const float* b2     = (const float*)d_in[13];

    float* out_x  = (float*)d_out;
    float* out_m  = out_x  + (size_t)NBL*DM;
    float* out_dt = out_m  + (size_t)NBL*DM;
    float* out_z  = out_dt + (size_t)NBL*NH;

    float *pxraw, *pyf, *pyb;
    __half *pu, *py2, *ph, *pff, *pwi, *pwo, *pw1, *pw2;
    cudaGetSymbolAddress((void**)&pxraw, g_xraw);
    cudaGetSymbolAddress((void**)&pyf, g_yf); cudaGetSymbolAddress((void**)&pyb, g_yb);
    cudaGetSymbolAddress((void**)&pu,  g_u);  cudaGetSymbolAddress((void**)&py2, g_y2);
    cudaGetSymbolAddress((void**)&ph,  g_h);  cudaGetSymbolAddress((void**)&pff, g_ff);
    cudaGetSymbolAddress((void**)&pwi, g_wi); cudaGetSymbolAddress((void**)&pwo, g_wo);
    cudaGetSymbolAddress((void**)&pw1, g_w1); cudaGetSymbolAddress((void**)&pw2, g_w2);

    cudaFuncSetAttribute(mma_gemm<0>, cudaFuncAttributeMaxDynamicSharedMemorySize, GSMEM_BYTES);
    cudaFuncSetAttribute(mma_gemm<1>, cudaFuncAttributeMaxDynamicSharedMemorySize, GSMEM_BYTES);
    cudaFuncSetAttribute(mma_gemm<2>, cudaFuncAttributeMaxDynamicSharedMemorySize, GSMEM_BYTES);
    cudaFuncSetAttribute(mma_gemm<3>, cudaFuncAttributeMaxDynamicSharedMemorySize, GSMEM_BYTES);

    dim3 wb(32,8);
    // 1) W_in transpose
    wconv_kernel<<<dim3((DPROJ+31)/32, DM/32),  wb>>>(W_in,  pwi, DM,  DPROJ);
    // 2) pre-norm -> fp16
    prenorm_kernel<<<NBL,128>>>(x, mask, pu);
    // 3) in-projection (fused: z, xBC, dt)
    mma_gemm<3><<<dim3((DPROJ+127)/128, NBL/128), 256, GSMEM_BYTES>>>(
        pu, pwi, DPROJ, DM, nullptr, nullptr, nullptr, nullptr,
        out_z, pxraw, out_dt, dt_bias);
    // 4) conv + silu + mask (profiled slot)
    conv_kernel<<<(int)(((long)NBL*(CONVD/4) + 255)/256), 256>>>(conv_w, conv_b, mask);
    // 5) bidirectional scan (monolithic, 4-way split)
    scan_kernel<<<dim3(2,NH,BATCH), 256>>>(out_dt, A_log, Dv, pyf, pyb);
    // 6) W_out transpose
    wconv_kernel<<<dim3((DM+31)/32,    DIN/32), wb>>>(W_out, pwo, DIN, DM);
    // 7) gated rmsnorm -> fp16
    gatednorm_kernel<<<NBL,256>>>(out_z, norm_w, py2);
    // 8) out projection -> m
    mma_gemm<0><<<dim3(DM/128, NBL/128), 256, GSMEM_BYTES>>>(
        py2, pwo, DM, DIN, out_m, nullptr, nullptr, nullptr,
        nullptr, nullptr, nullptr, nullptr);
    // 9) h = rmsnorm(2m) -> fp16
    postnorm_kernel<<<NBL,128>>>(out_m, ph);
    // 10) W1 transpose
    wconv_kernel<<<dim3((DFF+31)/32,   DM/32),  wb>>>(W1,    pw1, DM,  DFF);
    // 11) FFN up: gelu -> fp16
    mma_gemm<1><<<dim3(DFF/128, NBL/128), 256, GSMEM_BYTES>>>(
        ph, pw1, DFF, DM, nullptr, b1, nullptr, pff,
        nullptr, nullptr, nullptr, nullptr);
    // 12) W2 transpose
    wconv_kernel<<<dim3((DM+31)/32,    DFF/32), wb>>>(W2,    pw2, DFF, DM);
    // 13) FFN down + residual
    mma_gemm<2><<<dim3(DM/128, NBL/128), 256, GSMEM_BYTES>>>(
        pff, pw2, DM, DFF, out_x, b2, out_m, nullptr,
        nullptr, nullptr, nullptr, nullptr);
}

// round 15
// speedup vs baseline: 1.5172x; 1.5172x over previous
#include <cuda_runtime.h>
#include <cuda_fp16.h>
#include <math.h>
#include <stdint.h>

#define BATCH 8
#define SEQ   2048
#define NBL   (BATCH*SEQ)          // 16384
#define DM    512
#define DIN   1024
#define NH    16
#define HD    64
#define DS    64
#define CONVD 1152
#define DPROJ 2192
#define DFF   2048
#define EPSR  1e-6f

// ===================== scratch (static device; no cudaMalloc) =====================
static __device__ float g_xraw[(size_t)NBL*CONVD];
static __device__ float g_xbc[(size_t)NBL*CONVD];
static __device__ float g_yf[(size_t)NBL*DIN];
static __device__ float g_yb[(size_t)NBL*DIN];
// fp16 activations
static __device__ __half g_u[(size_t)NBL*DM];
static __device__ __half g_y2[(size_t)NBL*DIN];
static __device__ __half g_h[(size_t)NBL*DM];
static __device__ __half g_ff[(size_t)NBL*DFF];
// fp16 transposed weights [N,K]
static __device__ __half g_wi[(size_t)DPROJ*DM];
static __device__ __half g_wo[(size_t)DM*DIN];
static __device__ __half g_w1[(size_t)DFF*DM];
static __device__ __half g_w2[(size_t)DM*DFF];

// ===================== helpers =====================
__device__ __forceinline__ uint32_t smem_to_u32(const void* smem_ptr) {
    uint32_t addr;
    asm("{ .reg .u64 tmp; cvta.to.shared.u64 tmp, %1; cvt.u32.u64 %0, tmp; }"
        : "=r"(addr) : "l"(smem_ptr));
    return addr;
}
__device__ __forceinline__ void cp_async16(uint32_t dst, const void* src, uint32_t bytes){
    asm volatile("cp.async.cg.shared.global [%0], [%1], 16, %2;"
                 :: "r"(dst), "l"(src), "r"(bytes));
}
__device__ __forceinline__ void cp_async4(uint32_t dst, const void* src){
    asm volatile("cp.async.ca.shared.global [%0], [%1], 4;"
                 :: "r"(dst), "l"(src));
}
#define CP_COMMIT() asm volatile("cp.async.commit_group;")
#define CP_WAIT1()  asm volatile("cp.async.wait_group 1;")
#define CP_WAIT0()  asm volatile("cp.async.wait_group 0;")

__device__ __forceinline__ void ldm_x4(uint32_t addr, uint32_t& r0, uint32_t& r1,
                                       uint32_t& r2, uint32_t& r3){
    asm volatile("ldmatrix.sync.aligned.m8n8.x4.shared.b16 {%0,%1,%2,%3}, [%4];"
                 : "=r"(r0), "=r"(r1), "=r"(r2), "=r"(r3) : "r"(addr));
}
__device__ __forceinline__ void mma16816(float* c, const uint32_t* a, const uint32_t* b){
    asm volatile(
        "mma.sync.aligned.m16n8k16.row.col.f32.f16.f16.f32 "
        "{%0,%1,%2,%3}, {%4,%5,%6,%7}, {%8,%9}, {%0,%1,%2,%3};"
        : "+f"(c[0]), "+f"(c[1]), "+f"(c[2]), "+f"(c[3])
        : "r"(a[0]), "r"(a[1]), "r"(a[2]), "r"(a[3]), "r"(b[0]), "r"(b[1]));
}

__device__ __forceinline__ float siluf(float x){ return x / (1.f + expf(-x)); }
__device__ __forceinline__ float geluf(float x){
    float x3 = x*x*x;
    return 0.5f*x*(1.f + tanhf(0.7978845608028654f*(x + 0.044715f*x3)));
}
__device__ __forceinline__ float softplusf(float x){
    return fmaxf(x, 0.f) + log1pf(expf(-fabsf(x)));
}

// ===================== weight transpose: W[K,N] fp32 -> T[N,K] fp16 ==============
__global__ void wconv_kernel(const float* __restrict__ W,
                             __half* __restrict__ T, int K, int N){
    __shared__ float tile[32][33];
    int n0 = blockIdx.x*32, k0 = blockIdx.y*32;
    int tx = threadIdx.x, ty = threadIdx.y;
    #pragma unroll
    for (int i=0;i<32;i+=8){
        int k = k0+ty+i, n = n0+tx;
        tile[ty+i][tx] = (n < N) ? W[(size_t)k*N + n] : 0.f;
    }
    __syncthreads();
    #pragma unroll
    for (int i=0;i<32;i+=8){
        int n = n0+ty+i, k = k0+tx;
        if (n < N) T[(size_t)n*K + k] = __float2half(tile[tx][ty+i]);
    }
}

// ===================== fp16 HMMA GEMM, BK=64 (frozen) ============================
#define BK 64
#define LDSB 144
#define MAT_ELEMS (128*72)
#define STAGE_BYTES (2*MAT_ELEMS*2)
#define GSMEM_BYTES (3*STAGE_BYTES)

template<int MODE>
__global__ void __launch_bounds__(256,2)
mma_gemm(const __half* __restrict__ A, const __half* __restrict__ B,
         int N, int K,
         float* __restrict__ C, const float* __restrict__ bias,
         const float* __restrict__ res, __half* __restrict__ Oh,
         float* __restrict__ z_out, float* __restrict__ xraw,
         float* __restrict__ dt_out, const float* __restrict__ dtb)
{
    extern __shared__ __half smem[];
    const uint32_t sb = smem_to_u32(smem);
    const int tid = threadIdx.x;
    const int lane = tid & 31, wid = tid >> 5;
    const int row0 = blockIdx.y * 128;
    const int n0   = blockIdx.x * 128;
    const int wm0 = (wid & 3) * 32;
    const int wn0 = (wid >> 2) * 64;

    const uint32_t aoff = (uint32_t)((lane & 15) * LDSB + (lane >> 4) * 16);
    const uint32_t boff = (uint32_t)(((lane & 7) + ((lane & 16) >> 1)) * LDSB + (lane & 8) * 2);

    float acc[2][8][4];
    #pragma unroll
    for (int i=0;i<2;i++)
        #pragma unroll
        for (int j=0;j<8;j++)
            #pragma unroll
            for (int q=0;q<4;q++) acc[i][j][q]=0.f;

    const int nch = K / BK;

    auto issue = [&](int ch){
        const int k0 = ch * BK;
        uint32_t base = sb + (uint32_t)((ch % 3) * STAGE_BYTES);
        #pragma unroll
        for (int i=0;i<4;i++){
            int id = tid + i*256;
            int r = id >> 3, c8e = (id & 7) * 8;
            size_t g = (size_t)(row0 + r) * K + k0 + c8e;
            uint32_t so = (uint32_t)(r * LDSB + c8e * 2);
            cp_async16(base + so, A + g, 16);
        }
        #pragma unroll
        for (int i=0;i<4;i++){
            int id = tid + i*256;
            int r = id >> 3, c8e = (id & 7) * 8;
            int n = n0 + r;
            int valid = (n < N);
            size_t g = (size_t)(valid ? n : 0) * K + k0 + c8e;
            uint32_t so = (uint32_t)(r * LDSB + c8e * 2);
            cp_async16(base + (uint32_t)MAT_ELEMS*2 + so, B + g, valid ? 16u : 0u);
        }
        CP_COMMIT();
    };

    issue(0); if (nch > 1) issue(1);
    for (int ch = 0; ch < nch; ch++){
        if (ch + 1 < nch) CP_WAIT1(); else CP_WAIT0();
        __syncthreads();
        if (ch + 2 < nch) issue(ch + 2);

        const uint32_t base = sb + (uint32_t)((ch % 3) * STAGE_BYTES);
        const uint32_t bA = base;
        const uint32_t bB = base + (uint32_t)MAT_ELEMS*2;

        #pragma unroll
        for (int ks = 0; ks < BK; ks += 16){
            uint32_t a[2][4], b[8][2];
            #pragma unroll
            for (int mt = 0; mt < 2; mt++){
                uint32_t ao = (uint32_t)((wm0 + mt*16) * LDSB + ks*2) + aoff;
                ldm_x4(bA + ao, a[mt][0], a[mt][1], a[mt][2], a[mt][3]);
            }
            #pragma unroll
            for (int p = 0; p < 4; p++){
                uint32_t bo = (uint32_t)((wn0 + p*16) * LDSB + ks*2) + boff;
                ldm_x4(bB + bo, b[2*p][0], b[2*p][1], b[2*p+1][0], b[2*p+1][1]);
            }
            #pragma unroll
            for (int mt = 0; mt < 2; mt++)
                #pragma unroll
                for (int nt = 0; nt < 8; nt++)
                    mma16816(acc[mt][nt], a[mt], b[nt]);
        }
        __syncthreads();
    }

    const int rb = row0 + wm0 + (lane >> 2);
    const int cb = n0 + wn0 + (lane & 3) * 2;
    #pragma unroll
    for (int mt = 0; mt < 2; mt++){
        #pragma unroll
        for (int nt = 0; nt < 8; nt++){
            int c = cb + nt*8;
            if (c >= N) continue;
            #pragma unroll
            for (int half = 0; half < 2; half++){
                int r = rb + mt*16 + half*8;
                float v0 = acc[mt][nt][half*2+0];
                float v1 = acc[mt][nt][half*2+1];
                size_t o = (size_t)r*N + c;
                if (MODE == 0){
                    *(float2*)(C + o) = make_float2(v0, v1);
                } else if (MODE == 1){
                    v0 = geluf(v0 + bias[c]);
                    v1 = geluf(v1 + bias[c+1]);
                    __half2 hp; hp.x = __float2half(v0); hp.y = __float2half(v1);
                    *(__half2*)(Oh + o) = hp;
                } else if (MODE == 2){
                    float2 rv = *(const float2*)(res + o);
                    *(float2*)(C + o) = make_float2(v0 + bias[c]   + 2.f*rv.x,
                                                    v1 + bias[c+1] + 2.f*rv.y);
                } else {
                    if (c < DIN){
                        *(float2*)(z_out + (size_t)r*DIN + c) = make_float2(v0, v1);
                    } else if (c < DIN + CONVD){
                        *(float2*)(xraw + (size_t)r*CONVD + (c - DIN)) = make_float2(v0, v1);
                    } else {
                        int hh2 = c - (DIN + CONVD);
                        dt_out[(size_t)r*NH + hh2]     = softplusf(v0 + dtb[hh2]);
                        dt_out[(size_t)r*NH + hh2 + 1] = softplusf(v1 + dtb[hh2+1]);
                    }
                }
            }
        }
    }
}

// ===================== u = rmsnorm(x*mask) -> fp16 =====================
__global__ void __launch_bounds__(128) prenorm_kernel(const float* __restrict__ x,
                                                      const float* __restrict__ mask,
                                                      __half* __restrict__ u){
    int row = blockIdx.x; int t = threadIdx.x;
    float mk = mask[row];
    float4 a = ((const float4*)(x + (size_t)row*DM))[t];
    a.x*=mk; a.y*=mk; a.z*=mk; a.w*=mk;
    float ss = a.x*a.x + a.y*a.y + a.z*a.z + a.w*a.w;
    __shared__ float sh[4];
    #pragma unroll
    for (int o=16;o;o>>=1) ss += __shfl_xor_sync(0xffffffffu, ss, o);
    if ((t&31)==0) sh[t>>5] = ss;
    __syncthreads();
    float inv = rsqrtf((sh[0]+sh[1]+sh[2]+sh[3])*(1.f/DM) + EPSR);
    __half2 p0, p1;
    p0.x = __float2half(a.x*inv); p0.y = __float2half(a.y*inv);
    p1.x = __float2half(a.z*inv); p1.y = __float2half(a.w*inv);
    size_t o = (size_t)row*DM + t*4;
    *(__half2*)(u+o)   = p0;
    *(__half2*)(u+o+2) = p1;
}

// ===================== conv + silu + mask, float4 (frozen) =======================
__global__ void conv_kernel(const float* __restrict__ cw, const float* __restrict__ cb,
                            const float* __restrict__ mask){
    long idx = (long)blockIdx.x*blockDim.x + threadIdx.x;
    if (idx >= (long)NBL*(CONVD/4)) return;
    int c4 = (int)(idx % (CONVD/4));
    long bl = idx / (CONVD/4);
    int l = (int)(bl % SEQ);
    int c = c4 * 4;
    float4 w0 = *(const float4*)(cw + (size_t)c*4);
    float4 w1 = *(const float4*)(cw + (size_t)(c+1)*4);
    float4 w2 = *(const float4*)(cw + (size_t)(c+2)*4);
    float4 w3 = *(const float4*)(cw + (size_t)(c+3)*4);
    float4 acc = *(const float4*)(cb + c);
    float4 xt[4];
    #pragma unroll
    for (int i=0;i<4;i++){
        int ls = l + i - 3;
        if (ls >= 0) xt[i] = *(const float4*)(g_xraw + (size_t)(bl + (i-3))*CONVD + c);
        else         xt[i] = make_float4(0.f,0.f,0.f,0.f);
    }
    acc.x += xt[0].x*w0.x + xt[1].x*w0.y + xt[2].x*w0.z + xt[3].x*w0.w;
    acc.y += xt[0].y*w1.x + xt[1].y*w1.y + xt[2].y*w1.z + xt[3].y*w1.w;
    acc.z += xt[0].z*w2.x + xt[1].z*w2.y + xt[2].z*w2.z + xt[3].z*w2.w;
    acc.w += xt[0].w*w3.x + xt[1].w*w3.y + xt[2].w*w3.z + xt[3].w*w3.w;
    float mk = mask[bl];
    float4 o4;
    o4.x = siluf(acc.x)*mk; o4.y = siluf(acc.y)*mk;
    o4.z = siluf(acc.z)*mk; o4.w = siluf(acc.w)*mk;
    *(float4*)(g_xbc + (size_t)bl*CONVD + c) = o4;
}

// ===================== bidirectional SSM scan, cp.async double-buffered ==========
// grid (2, NH, BATCH), 128 threads. Thread pair (2p,2p+1) owns state row p;
// each handles 32 of 64 state cols as 8 float4. Tile CT=64, 2 smem buffers;
// next tile streams in via cp.async while current tile computes.
#define SCT 64
#define SBUF 4096                       // floats per (array,buffer) = SCT*64
#define SCAN_SMEM_FLOATS (6*SBUF + 2*SCT)
#define SCAN_SMEM_BYTES  (SCAN_SMEM_FLOATS*4)   // 98816

__global__ void __launch_bounds__(128) scan_kernel(const float* __restrict__ dtb,
                                                   const float* __restrict__ A_log,
                                                   const float* __restrict__ Dv,
                                                   float* __restrict__ yf,
                                                   float* __restrict__ yb){
    extern __shared__ float sm[];
    const uint32_t sb = smem_to_u32(sm);
    const int dir = blockIdx.x;
    const int h   = blockIdx.y;
    const int b   = blockIdx.z;
    const int tid = threadIdx.x;
    const int p    = tid >> 1;
    const int half = tid & 1;
    const int nbase = half << 5;
    const float Ah = -expf(A_log[h]);
    const float Dh = Dv[h];
    float st[32];
    #pragma unroll
    for (int j=0;j<32;j++) st[j]=0.f;
    const size_t base = (size_t)b*SEQ;
    float* yout = dir ? yb : yf;

    // float-index bases: B:[0,2*SBUF) C:[2*SBUF,4*SBUF) X:[4*SBUF,6*SBUF) T:[6*SBUF,..)
    auto issue_tile = [&](int tile, int buf){
        const int t0 = tile * SCT;
        const uint32_t bB = sb + 4u*(0*SBUF + buf*SBUF);
        const uint32_t bC = sb + 4u*(2*SBUF + buf*SBUF);
        const uint32_t bX = sb + 4u*(4*SBUF + buf*SBUF);
        #pragma unroll
        for (int i=0;i<8;i++){
            int idx = tid + i*128;          // 0..1023
            int tt = idx >> 4, q = idx & 15;
            int t = dir ? (SEQ-1-(t0+tt)) : (t0+tt);
            const float* src = g_xbc + (base + t)*(size_t)CONVD;
            uint32_t so = (uint32_t)(tt*256 + q*16);
            cp_async16(bB + so, src + DIN       + q*4, 16);
            cp_async16(bC + so, src + DIN + DS  + q*4, 16);
            cp_async16(bX + so, src + h*HD      + q*4, 16);
        }
        if (tid < SCT){
            int t = dir ? (SEQ-1-(t0+tid)) : (t0+tid);
            cp_async4(sb + 4u*(6*SBUF + buf*SCT + tid), dtb + (base + t)*NH + h);
        }
        CP_COMMIT();
    };

    issue_tile(0, 0);
    const int ntiles = SEQ / SCT;
    for (int tile = 0; tile < ntiles; tile++){
        const int buf = tile & 1;
        CP_WAIT0();
        __syncthreads();
        if (tile + 1 < ntiles) issue_tile(tile + 1, buf ^ 1);

        const float* Bbuf = sm + 0*SBUF + buf*SBUF;
        const float* Cbuf = sm + 2*SBUF + buf*SBUF;
        const float* Xbuf = sm + 4*SBUF + buf*SBUF;
        const float* Tbuf = sm + 6*SBUF + buf*SCT;
        const int t0 = tile * SCT;
        for (int tt=0; tt<SCT; tt++){
            float dtv = Tbuf[tt];
            float dA  = __expf(dtv*Ah);
            float xv  = Xbuf[tt*64 + p];
            float dtx = dtv * xv;
            const float4* Bp = (const float4*)(Bbuf + tt*64 + nbase);
            const float4* Cp = (const float4*)(Cbuf + tt*64 + nbase);
            float y0=0.f, y1=0.f, y2v=0.f, y3=0.f;
            #pragma unroll
            for (int j=0;j<8;j++){
                float4 bv = Bp[j];
                float4 cv = Cp[j];
                st[4*j+0] = fmaf(dA, st[4*j+0], dtx*bv.x); y0  = fmaf(st[4*j+0], cv.x, y0);
                st[4*j+1] = fmaf(dA, st[4*j+1], dtx*bv.y); y1  = fmaf(st[4*j+1], cv.y, y1);
                st[4*j+2] = fmaf(dA, st[4*j+2], dtx*bv.z); y2v = fmaf(st[4*j+2], cv.z, y2v);
                st[4*j+3] = fmaf(dA, st[4*j+3], dtx*bv.w); y3  = fmaf(st[4*j+3], cv.w, y3);
            }
            float y = (y0+y1) + (y2v+y3);
            y += __shfl_xor_sync(0xffffffffu, y, 1);
            if (half == 0){
                int t = dir ? (SEQ-1-(t0+tt)) : (t0+tt);
                float yv = y;
                if (dir==0) yv = fmaf(Dh, xv, yv);
                yout[(base + t)*(size_t)DIN + h*HD + p] = yv;
            }
        }
        __syncthreads();
    }
}

// ===================== y2 = rmsnorm((yf+yb) * silu(z)) * norm_w -> fp16 ==========
__global__ void __launch_bounds__(256) gatednorm_kernel(const float* __restrict__ z,
                                                        const float* __restrict__ w,
                                                        __half* __restrict__ y2){
    int row = blockIdx.x; int t = threadIdx.x;
    float4 ya = ((const float4*)(g_yf + (size_t)row*DIN))[t];
    float4 ybv = ((const float4*)(g_yb + (size_t)row*DIN))[t];
    float4 zv = ((const float4*)(z    + (size_t)row*DIN))[t];
    float4 v;
    v.x = (ya.x + ybv.x) * siluf(zv.x);
    v.y = (ya.y + ybv.y) * siluf(zv.y);
    v.z = (ya.z + ybv.z) * siluf(zv.z);
    v.w = (ya.w + ybv.w) * siluf(zv.w);
    float ss = v.x*v.x + v.y*v.y + v.z*v.z + v.w*v.w;
    __shared__ float sh[8];
    #pragma unroll
    for (int o=16;o;o>>=1) ss += __shfl_xor_sync(0xffffffffu, ss, o);
    if ((t&31)==0) sh[t>>5] = ss;
    __syncthreads();
    float tot = sh[0]+sh[1]+sh[2]+sh[3]+sh[4]+sh[5]+sh[6]+sh[7];
    float inv = rsqrtf(tot*(1.f/DIN) + EPSR);
    float4 wv = ((const float4*)w)[t];
    __half2 p0, p1;
    p0.x = __float2half(v.x*inv*wv.x); p0.y = __float2half(v.y*inv*wv.y);
    p1.x = __float2half(v.z*inv*wv.z); p1.y = __float2half(v.w*inv*wv.w);
    size_t o = (size_t)row*DIN + t*4;
    *(__half2*)(y2+o)   = p0;
    *(__half2*)(y2+o+2) = p1;
}

// ===================== h = rmsnorm(2*m) -> fp16 =====================
__global__ void __launch_bounds__(128) postnorm_kernel(const float* __restrict__ m,
                                                       __half* __restrict__ hbuf){
    int row = blockIdx.x; int t = threadIdx.x;
    float4 mv = ((const float4*)(m + (size_t)row*DM))[t];
    float4 v = make_float4(2.f*mv.x, 2.f*mv.y, 2.f*mv.z, 2.f*mv.w);
    float ss = v.x*v.x + v.y*v.y + v.z*v.z + v.w*v.w;
    __shared__ float sh[4];
    #pragma unroll
    for (int o=16;o;o>>=1) ss += __shfl_xor_sync(0xffffffffu, ss, o);
    if ((t&31)==0) sh[t>>5] = ss;
    __syncthreads();
    float inv = rsqrtf((sh[0]+sh[1]+sh[2]+sh[3])*(1.f/DM) + EPSR);
    __half2 p0, p1;
    p0.x = __float2half(v.x*inv); p0.y = __float2half(v.y*inv);
    p1.x = __float2half(v.z*inv); p1.y = __float2half(v.w*inv);
    size_t o = (size_t)row*DM + t*4;
    *(__half2*)(hbuf+o)   = p0;
    *(__half2*)(hbuf+o+2) = p1;
}

extern "C" void kernel_launch(void* const* d_in, const int* in_sizes, int n_in,
                              void* d_out, int out_size){
    const float* x      = (const float*)d_in[0];
    const float* mask   = (const float*)d_in[1];
    const float* W_in   = (const float*)d_in[2];
    const float* conv_w = (const float*)d_in[3];
    const float* conv_b = (const float*)d_in[4];
    const float* dt_bias= (const float*)d_in[5];
    const float* A_log  = (const float*)d_in[6];
    const float* Dv     = (const float*)d_in[7];
    const float* norm_w = (const float*)d_in[8];
    const float* W_out  = (const float*)d_in[9];
    const float* W1     = (const float*)d_in[10];
    const float* b1     = (const float*)d_in[11];
    const float* W2     = (const float*)d_in[12];
    const float* b2     = (const float*)d_in[13];

    float* out_x  = (float*)d_out;
    float* out_m  = out_x  + (size_t)NBL*DM;
    float* out_dt = out_m  + (size_t)NBL*DM;
    float* out_z  = out_dt + (size_t)NBL*NH;

    float *pxraw, *pyf, *pyb;
    __half *pu, *py2, *ph, *pff, *pwi, *pwo, *pw1, *pw2;
    cudaGetSymbolAddress((void**)&pxraw, g_xraw);
    cudaGetSymbolAddress((void**)&pyf, g_yf); cudaGetSymbolAddress((void**)&pyb, g_yb);
    cudaGetSymbolAddress((void**)&pu,  g_u);  cudaGetSymbolAddress((void**)&py2, g_y2);
    cudaGetSymbolAddress((void**)&ph,  g_h);  cudaGetSymbolAddress((void**)&pff, g_ff);
    cudaGetSymbolAddress((void**)&pwi, g_wi); cudaGetSymbolAddress((void**)&pwo, g_wo);
    cudaGetSymbolAddress((void**)&pw1, g_w1); cudaGetSymbolAddress((void**)&pw2, g_w2);

    cudaFuncSetAttribute(mma_gemm<0>, cudaFuncAttributeMaxDynamicSharedMemorySize, GSMEM_BYTES);
    cudaFuncSetAttribute(mma_gemm<1>, cudaFuncAttributeMaxDynamicSharedMemorySize, GSMEM_BYTES);
    cudaFuncSetAttribute(mma_gemm<2>, cudaFuncAttributeMaxDynamicSharedMemorySize, GSMEM_BYTES);
    cudaFuncSetAttribute(mma_gemm<3>, cudaFuncAttributeMaxDynamicSharedMemorySize, GSMEM_BYTES);
    cudaFuncSetAttribute(scan_kernel, cudaFuncAttributeMaxDynamicSharedMemorySize, SCAN_SMEM_BYTES);

    dim3 wb(32,8);
    // 1) W_in transpose
    wconv_kernel<<<dim3((DPROJ+31)/32, DM/32),  wb>>>(W_in,  pwi, DM,  DPROJ);
    // 2) pre-norm -> fp16
    prenorm_kernel<<<NBL,128>>>(x, mask, pu);
    // 3) in-projection (fused: z, xBC, dt)
    mma_gemm<3><<<dim3((DPROJ+127)/128, NBL/128), 256, GSMEM_BYTES>>>(
        pu, pwi, DPROJ, DM, nullptr, nullptr, nullptr, nullptr,
        out_z, pxraw, out_dt, dt_bias);
    // 4) conv + silu + mask (profiled slot)
    conv_kernel<<<(int)(((long)NBL*(CONVD/4) + 255)/256), 256>>>(conv_w, conv_b, mask);
    // 5) bidirectional scan (double-buffered)
    scan_kernel<<<dim3(2,NH,BATCH), 128, SCAN_SMEM_BYTES>>>(out_dt, A_log, Dv, pyf, pyb);
    // 6) W_out transpose
    wconv_kernel<<<dim3((DM+31)/32,    DIN/32), wb>>>(W_out, pwo, DIN, DM);
    // 7) gated rmsnorm -> fp16
    gatednorm_kernel<<<NBL,256>>>(out_z, norm_w, py2);
    // 8) out projection -> m
    mma_gemm<0><<<dim3(DM/128, NBL/128), 256, GSMEM_BYTES>>>(
        py2, pwo, DM, DIN, out_m, nullptr, nullptr, nullptr,
        nullptr, nullptr, nullptr, nullptr);
    // 9) h = rmsnorm(2m) -> fp16
    postnorm_kernel<<<NBL,128>>>(out_m, ph);
    // 10) W1 transpose
    wconv_kernel<<<dim3((DFF+31)/32,   DM/32),  wb>>>(W1,    pw1, DM,  DFF);
    // 11) FFN up: gelu -> fp16
    mma_gemm<1><<<dim3(DFF/128, NBL/128), 256, GSMEM_BYTES>>>(
        ph, pw1, DFF, DM, nullptr, b1, nullptr, pff,
        nullptr, nullptr, nullptr, nullptr);
    // 12) W2 transpose
    wconv_kernel<<<dim3((DM+31)/32,    DFF/32), wb>>>(W2,    pw2, DFF, DM);
    // 13) FFN down + residual
    mma_gemm<2><<<dim3(DM/128, NBL/128), 256, GSMEM_BYTES>>>(
        pff, pw2, DM, DFF, out_x, b2, out_m, nullptr,
        nullptr, nullptr, nullptr, nullptr);
}

// round 16
// speedup vs baseline: 1.7708x; 1.1672x over previous
#include <cuda_runtime.h>
#include <cuda_fp16.h>
#include <math.h>
#include <stdint.h>

#define BATCH 8
#define SEQ   2048
#define NBL   (BATCH*SEQ)          // 16384
#define DM    512
#define DIN   1024
#define NH    16
#define HD    64
#define DS    64
#define CONVD 1152
#define DPROJ 2192
#define DFF   2048
#define EPSR  1e-6f
#define LC    64                   // SSD chunk length
#define NCHK  (SEQ/LC)             // 32 chunks

// ===================== scratch (static device; no cudaMalloc) =====================
static __device__ float g_xraw[(size_t)NBL*CONVD];
static __device__ float g_xbc[(size_t)NBL*CONVD];
static __device__ float g_yf[(size_t)NBL*DIN];
static __device__ float g_yb[(size_t)NBL*DIN];
static __device__ float g_sum[(size_t)2*NH*BATCH*NCHK*HD*DS];  // chunk end-states [p][n]
static __device__ float g_pa[2*NH*BATCH*NCHK];                 // chunk decay
// fp16 activations
static __device__ __half g_u[(size_t)NBL*DM];
static __device__ __half g_y2[(size_t)NBL*DIN];
static __device__ __half g_h[(size_t)NBL*DM];
static __device__ __half g_ff[(size_t)NBL*DFF];
// fp16 transposed weights [N,K]
static __device__ __half g_wi[(size_t)DPROJ*DM];
static __device__ __half g_wo[(size_t)DM*DIN];
static __device__ __half g_w1[(size_t)DFF*DM];
static __device__ __half g_w2[(size_t)DM*DFF];

// ===================== helpers =====================
__device__ __forceinline__ uint32_t smem_to_u32(const void* smem_ptr) {
    uint32_t addr;
    asm("{ .reg .u64 tmp; cvta.to.shared.u64 tmp, %1; cvt.u32.u64 %0, tmp; }"
        : "=r"(addr) : "l"(smem_ptr));
    return addr;
}
__device__ __forceinline__ void cp_async16(uint32_t dst, const void* src, uint32_t bytes){
    asm volatile("cp.async.cg.shared.global [%0], [%1], 16, %2;"
                 :: "r"(dst), "l"(src), "r"(bytes));
}
#define CP_COMMIT() asm volatile("cp.async.commit_group;")
#define CP_WAIT1()  asm volatile("cp.async.wait_group 1;")
#define CP_WAIT0()  asm volatile("cp.async.wait_group 0;")

__device__ __forceinline__ void ldm_x4(uint32_t addr, uint32_t& r0, uint32_t& r1,
                                       uint32_t& r2, uint32_t& r3){
    asm volatile("ldmatrix.sync.aligned.m8n8.x4.shared.b16 {%0,%1,%2,%3}, [%4];"
                 : "=r"(r0), "=r"(r1), "=r"(r2), "=r"(r3) : "r"(addr));
}
__device__ __forceinline__ void mma16816(float* c, const uint32_t* a, const uint32_t* b){
    asm volatile(
        "mma.sync.aligned.m16n8k16.row.col.f32.f16.f16.f32 "
        "{%0,%1,%2,%3}, {%4,%5,%6,%7}, {%8,%9}, {%0,%1,%2,%3};"
        : "+f"(c[0]), "+f"(c[1]), "+f"(c[2]), "+f"(c[3])
        : "r"(a[0]), "r"(a[1]), "r"(a[2]), "r"(a[3]), "r"(b[0]), "r"(b[1]));
}

__device__ __forceinline__ float siluf(float x){ return x / (1.f + expf(-x)); }
__device__ __forceinline__ float geluf(float x){
    float x3 = x*x*x;
    return 0.5f*x*(1.f + tanhf(0.7978845608028654f*(x + 0.044715f*x3)));
}
__device__ __forceinline__ float softplusf(float x){
    return fmaxf(x, 0.f) + log1pf(expf(-fabsf(x)));
}

#define LDSB 144    // smem row stride bytes (72 halves) -- shared by GEMM + SSD

// 64x64x64 fp16 GEMM helper: 4 warps, warp wid covers rows [wid*16, wid*16+16).
// A: [m][k] k-contiguous rows of 72 halves; B: [n][k] k-contiguous rows of 72 halves.
__device__ __forceinline__ void gemm64(uint32_t Abase, uint32_t Bbase, int wm0,
                                       uint32_t aoff, uint32_t boff, float acc[8][4]){
    #pragma unroll
    for (int ks = 0; ks < 64; ks += 16){
        uint32_t a[4];
        ldm_x4(Abase + (uint32_t)(wm0*LDSB + ks*2) + aoff, a[0], a[1], a[2], a[3]);
        uint32_t bfr[8][2];
        #pragma unroll
        for (int p4 = 0; p4 < 4; p4++)
            ldm_x4(Bbase + (uint32_t)((p4*16)*LDSB + ks*2) + boff,
                   bfr[2*p4][0], bfr[2*p4][1], bfr[2*p4+1][0], bfr[2*p4+1][1]);
        #pragma unroll
        for (int nt = 0; nt < 8; nt++)
            mma16816(acc[nt], a, bfr[nt]);
    }
}

// ===================== weight transpose: W[K,N] fp32 -> T[N,K] fp16 ==============
__global__ void wconv_kernel(const float* __restrict__ W,
                             __half* __restrict__ T, int K, int N){
    __shared__ float tile[32][33];
    int n0 = blockIdx.x*32, k0 = blockIdx.y*32;
    int tx = threadIdx.x, ty = threadIdx.y;
    #pragma unroll
    for (int i=0;i<32;i+=8){
        int k = k0+ty+i, n = n0+tx;
        tile[ty+i][tx] = (n < N) ? W[(size_t)k*N + n] : 0.f;
    }
    __syncthreads();
    #pragma unroll
    for (int i=0;i<32;i+=8){
        int n = n0+ty+i, k = k0+tx;
        if (n < N) T[(size_t)n*K + k] = __float2half(tile[tx][ty+i]);
    }
}

// ===================== fp16 HMMA GEMM, BK=64 (frozen) ============================
#define BK 64
#define MAT_ELEMS (128*72)
#define STAGE_BYTES (2*MAT_ELEMS*2)
#define GSMEM_BYTES (3*STAGE_BYTES)

template<int MODE>
__global__ void __launch_bounds__(256,2)
mma_gemm(const __half* __restrict__ A, const __half* __restrict__ B,
         int N, int K,
         float* __restrict__ C, const float* __restrict__ bias,
         const float* __restrict__ res, __half* __restrict__ Oh,
         float* __restrict__ z_out, float* __restrict__ xraw,
         float* __restrict__ dt_out, const float* __restrict__ dtb)
{
    extern __shared__ __half smem[];
    const uint32_t sb = smem_to_u32(smem);
    const int tid = threadIdx.x;
    const int lane = tid & 31, wid = tid >> 5;
    const int row0 = blockIdx.y * 128;
    const int n0   = blockIdx.x * 128;
    const int wm0 = (wid & 3) * 32;
    const int wn0 = (wid >> 2) * 64;

    const uint32_t aoff = (uint32_t)((lane & 15) * LDSB + (lane >> 4) * 16);
    const uint32_t boff = (uint32_t)(((lane & 7) + ((lane & 16) >> 1)) * LDSB + (lane & 8) * 2);

    float acc[2][8][4];
    #pragma unroll
    for (int i=0;i<2;i++)
        #pragma unroll
        for (int j=0;j<8;j++)
            #pragma unroll
            for (int q=0;q<4;q++) acc[i][j][q]=0.f;

    const int nch = K / BK;

    auto issue = [&](int ch){
        const int k0 = ch * BK;
        uint32_t base = sb + (uint32_t)((ch % 3) * STAGE_BYTES);
        #pragma unroll
        for (int i=0;i<4;i++){
            int id = tid + i*256;
            int r = id >> 3, c8e = (id & 7) * 8;
            size_t g = (size_t)(row0 + r) * K + k0 + c8e;
            uint32_t so = (uint32_t)(r * LDSB + c8e * 2);
            cp_async16(base + so, A + g, 16);
        }
        #pragma unroll
        for (int i=0;i<4;i++){
            int id = tid + i*256;
            int r = id >> 3, c8e = (id & 7) * 8;
            int n = n0 + r;
            int valid = (n < N);
            size_t g = (size_t)(valid ? n : 0) * K + k0 + c8e;
            uint32_t so = (uint32_t)(r * LDSB + c8e * 2);
            cp_async16(base + (uint32_t)MAT_ELEMS*2 + so, B + g, valid ? 16u : 0u);
        }
        CP_COMMIT();
    };

    issue(0); if (nch > 1) issue(1);
    for (int ch = 0; ch < nch; ch++){
        if (ch + 1 < nch) CP_WAIT1(); else CP_WAIT0();
        __syncthreads();
        if (ch + 2 < nch) issue(ch + 2);

        const uint32_t base = sb + (uint32_t)((ch % 3) * STAGE_BYTES);
        const uint32_t bA = base;
        const uint32_t bB = base + (uint32_t)MAT_ELEMS*2;

        #pragma unroll
        for (int ks = 0; ks < BK; ks += 16){
            uint32_t a[2][4], b[8][2];
            #pragma unroll
            for (int mt = 0; mt < 2; mt++){
                uint32_t ao = (uint32_t)((wm0 + mt*16) * LDSB + ks*2) + aoff;
                ldm_x4(bA + ao, a[mt][0], a[mt][1], a[mt][2], a[mt][3]);
            }
            #pragma unroll
            for (int p = 0; p < 4; p++){
                uint32_t bo = (uint32_t)((wn0 + p*16) * LDSB + ks*2) + boff;
                ldm_x4(bB + bo, b[2*p][0], b[2*p][1], b[2*p+1][0], b[2*p+1][1]);
            }
            #pragma unroll
            for (int mt = 0; mt < 2; mt++)
                #pragma unroll
                for (int nt = 0; nt < 8; nt++)
                    mma16816(acc[mt][nt], a[mt], b[nt]);
        }
        __syncthreads();
    }

    const int rb = row0 + wm0 + (lane >> 2);
    const int cb = n0 + wn0 + (lane & 3) * 2;
    #pragma unroll
    for (int mt = 0; mt < 2; mt++){
        #pragma unroll
        for (int nt = 0; nt < 8; nt++){
            int c = cb + nt*8;
            if (c >= N) continue;
            #pragma unroll
            for (int half = 0; half < 2; half++){
                int r = rb + mt*16 + half*8;
                float v0 = acc[mt][nt][half*2+0];
                float v1 = acc[mt][nt][half*2+1];
                size_t o = (size_t)r*N + c;
                if (MODE == 0){
                    *(float2*)(C + o) = make_float2(v0, v1);
                } else if (MODE == 1){
                    v0 = geluf(v0 + bias[c]);
                    v1 = geluf(v1 + bias[c+1]);
                    __half2 hp; hp.x = __float2half(v0); hp.y = __float2half(v1);
                    *(__half2*)(Oh + o) = hp;
                } else if (MODE == 2){
                    float2 rv = *(const float2*)(res + o);
                    *(float2*)(C + o) = make_float2(v0 + bias[c]   + 2.f*rv.x,
                                                    v1 + bias[c+1] + 2.f*rv.y);
                } else {
                    if (c < DIN){
                        *(float2*)(z_out + (size_t)r*DIN + c) = make_float2(v0, v1);
                    } else if (c < DIN + CONVD){
                        *(float2*)(xraw + (size_t)r*CONVD + (c - DIN)) = make_float2(v0, v1);
                    } else {
                        int hh2 = c - (DIN + CONVD);
                        dt_out[(size_t)r*NH + hh2]     = softplusf(v0 + dtb[hh2]);
                        dt_out[(size_t)r*NH + hh2 + 1] = softplusf(v1 + dtb[hh2+1]);
                    }
                }
            }
        }
    }
}

// ===================== u = rmsnorm(x*mask) -> fp16 =====================
__global__ void __launch_bounds__(128) prenorm_kernel(const float* __restrict__ x,
                                                      const float* __restrict__ mask,
                                                      __half* __restrict__ u){
    int row = blockIdx.x; int t = threadIdx.x;
    float mk = mask[row];
    float4 a = ((const float4*)(x + (size_t)row*DM))[t];
    a.x*=mk; a.y*=mk; a.z*=mk; a.w*=mk;
    float ss = a.x*a.x + a.y*a.y + a.z*a.z + a.w*a.w;
    __shared__ float sh[4];
    #pragma unroll
    for (int o=16;o;o>>=1) ss += __shfl_xor_sync(0xffffffffu, ss, o);
    if ((t&31)==0) sh[t>>5] = ss;
    __syncthreads();
    float inv = rsqrtf((sh[0]+sh[1]+sh[2]+sh[3])*(1.f/DM) + EPSR);
    __half2 p0, p1;
    p0.x = __float2half(a.x*inv); p0.y = __float2half(a.y*inv);
    p1.x = __float2half(a.z*inv); p1.y = __float2half(a.w*inv);
    size_t o = (size_t)row*DM + t*4;
    *(__half2*)(u+o)   = p0;
    *(__half2*)(u+o+2) = p1;
}

// ===================== conv + silu + mask, float4 (frozen) =======================
__global__ void conv_kernel(const float* __restrict__ cw, const float* __restrict__ cb,
                            const float* __restrict__ mask){
    long idx = (long)blockIdx.x*blockDim.x + threadIdx.x;
    if (idx >= (long)NBL*(CONVD/4)) return;
    int c4 = (int)(idx % (CONVD/4));
    long bl = idx / (CONVD/4);
    int l = (int)(bl % SEQ);
    int c = c4 * 4;
    float4 w0 = *(const float4*)(cw + (size_t)c*4);
    float4 w1 = *(const float4*)(cw + (size_t)(c+1)*4);
    float4 w2 = *(const float4*)(cw + (size_t)(c+2)*4);
    float4 w3 = *(const float4*)(cw + (size_t)(c+3)*4);
    float4 acc = *(const float4*)(cb + c);
    float4 xt[4];
    #pragma unroll
    for (int i=0;i<4;i++){
        int ls = l + i - 3;
        if (ls >= 0) xt[i] = *(const float4*)(g_xraw + (size_t)(bl + (i-3))*CONVD + c);
        else         xt[i] = make_float4(0.f,0.f,0.f,0.f);
    }
    acc.x += xt[0].x*w0.x + xt[1].x*w0.y + xt[2].x*w0.z + xt[3].x*w0.w;
    acc.y += xt[0].y*w1.x + xt[1].y*w1.y + xt[2].y*w1.z + xt[3].y*w1.w;
    acc.z += xt[0].z*w2.x + xt[1].z*w2.y + xt[2].z*w2.z + xt[3].z*w2.w;
    acc.w += xt[0].w*w3.x + xt[1].w*w3.y + xt[2].w*w3.z + xt[3].w*w3.w;
    float mk = mask[bl];
    float4 o4;
    o4.x = siluf(acc.x)*mk; o4.y = siluf(acc.y)*mk;
    o4.z = siluf(acc.z)*mk; o4.w = siluf(acc.w)*mk;
    *(float4*)(g_xbc + (size_t)bl*CONVD + c) = o4;
}

// ===================== SSD scan, stage 1: per-chunk tensor-core ==================
// grid (2*NCHK, NH, BATCH), 128 threads (4 warps).
// Y_intra = M(G) @ X (+D*x for fwd), chunk state S = (W.B)^T @ X -> g_sum[p][n],
// chunk decay -> g_pa.
__global__ void __launch_bounds__(128) ssd1_kernel(const float* __restrict__ dtb,
                                                   const float* __restrict__ A_log,
                                                   const float* __restrict__ Dv,
                                                   float* __restrict__ yf,
                                                   float* __restrict__ yb){
    __shared__ __half sC[64*72];
    __shared__ __half sB[64*72];
    __shared__ __half sXt[64*72];     // [p][t]
    __shared__ __half sBwT[64*72];    // [n][t]
    __shared__ __half sM[64*72];      // [t][s]
    __shared__ float dts[64], Dss[64], Pss[64];
    __shared__ float w0tot;

    const int dir = blockIdx.x & 1;
    const int c   = blockIdx.x >> 1;
    const int h   = blockIdx.y;
    const int b   = blockIdx.z;
    const int tid = threadIdx.x;
    const int lane = tid & 31, wid = tid >> 5;
    const float Ah = -expf(A_log[h]);
    const float Dh = Dv[h];
    const size_t base = (size_t)b*SEQ;
    float* yout = dir ? yb : yf;

    const uint32_t aoff = (uint32_t)((lane & 15) * LDSB + (lane >> 4) * 16);
    const uint32_t boff = (uint32_t)(((lane & 7) + ((lane & 16) >> 1)) * LDSB + (lane & 8) * 2);
    const uint32_t uC   = smem_to_u32(sC);
    const uint32_t uB   = smem_to_u32(sB);
    const uint32_t uXt  = smem_to_u32(sXt);
    const uint32_t uBwT = smem_to_u32(sBwT);
    const uint32_t uM   = smem_to_u32(sM);

    // --- dt load + inclusive cumsum (warps 0,1) ---
    if (wid < 2){
        int i = wid*32 + lane;
        int tl = c*LC + i;
        int t = dir ? (SEQ-1-tl) : tl;
        float d = dtb[(base + t)*NH + h];
        dts[i] = d;
        float s = d;
        #pragma unroll
        for (int o=1;o<32;o<<=1){
            float v = __shfl_up_sync(0xffffffffu, s, o);
            if (lane >= o) s += v;
        }
        Dss[i] = s;
        if (wid == 0 && lane == 31) w0tot = s;
    }
    __syncthreads();
    if (wid < 2){
        int i = wid*32 + lane;
        float s = Dss[i] + (wid ? w0tot : 0.f);
        Dss[i] = s;
        Pss[i] = __expf(Ah * s);
    }
    __syncthreads();
    const float Dlast = Dss[63];

    // --- load B, C, X; build fp16 tiles ---
    for (int idx = tid; idx < 64*16; idx += 128){
        int t = idx >> 4, q = idx & 15;
        int tl = c*LC + t;
        int tg = dir ? (SEQ-1-tl) : tl;
        const float* src = g_xbc + (base + tg)*(size_t)CONVD;
        float4 bv = *(const float4*)(src + DIN + q*4);
        float4 cv = *(const float4*)(src + DIN + DS + q*4);
        float4 xv = *(const float4*)(src + h*HD + q*4);
        __half2 hb0, hb1, hc0, hc1;
        hb0.x=__float2half(bv.x); hb0.y=__float2half(bv.y);
        hb1.x=__float2half(bv.z); hb1.y=__float2half(bv.w);
        hc0.x=__float2half(cv.x); hc0.y=__float2half(cv.y);
        hc1.x=__float2half(cv.z); hc1.y=__float2half(cv.w);
        *(__half2*)(sB + t*72 + q*4)     = hb0;
        *(__half2*)(sB + t*72 + q*4 + 2) = hb1;
        *(__half2*)(sC + t*72 + q*4)     = hc0;
        *(__half2*)(sC + t*72 + q*4 + 2) = hc1;
        // X transposed: [p][t]
        sXt[(q*4+0)*72 + t] = __float2half(xv.x);
        sXt[(q*4+1)*72 + t] = __float2half(xv.y);
        sXt[(q*4+2)*72 + t] = __float2half(xv.z);
        sXt[(q*4+3)*72 + t] = __float2half(xv.w);
        // (W.B)^T: [n][t], W_t = exp(Ah*(Dlast - D_t)) * dt_t
        float w = __expf(Ah*(Dlast - Dss[t])) * dts[t];
        sBwT[(q*4+0)*72 + t] = __float2half(w*bv.x);
        sBwT[(q*4+1)*72 + t] = __float2half(w*bv.y);
        sBwT[(q*4+2)*72 + t] = __float2half(w*bv.z);
        sBwT[(q*4+3)*72 + t] = __float2half(w*bv.w);
    }
    __syncthreads();

    const int wm0 = wid * 16;
    // --- GEMM1: G = C @ B^T ---
    float acc[8][4];
    #pragma unroll
    for (int i=0;i<8;i++){ acc[i][0]=0.f; acc[i][1]=0.f; acc[i][2]=0.f; acc[i][3]=0.f; }
    gemm64(uC, uB, wm0, aoff, boff, acc);

    // --- mask -> M fp16 ---
    {
        const int tr = wm0 + (lane >> 2);
        const int sc = (lane & 3) * 2;
        #pragma unroll
        for (int hh = 0; hh < 2; hh++){
            int t_l = tr + hh*8;
            float Dt = Dss[t_l];
            #pragma unroll
            for (int nt = 0; nt < 8; nt++){
                #pragma unroll
                for (int j = 0; j < 2; j++){
                    int s = nt*8 + sc + j;
                    float g = acc[nt][hh*2+j];
                    float m = (t_l >= s) ? __expf(Ah*(Dt - Dss[s])) * dts[s] * g : 0.f;
                    sM[t_l*72 + s] = __float2half(m);
                }
            }
        }
    }
    __syncthreads();

    // --- GEMM2: Y = M @ X  (+ D*x for fwd) ---
    #pragma unroll
    for (int i=0;i<8;i++){ acc[i][0]=0.f; acc[i][1]=0.f; acc[i][2]=0.f; acc[i][3]=0.f; }
    gemm64(uM, uXt, wm0, aoff, boff, acc);
    {
        const int tr = wm0 + (lane >> 2);
        const int pc = (lane & 3) * 2;
        #pragma unroll
        for (int hh = 0; hh < 2; hh++){
            int t_l = tr + hh*8;
            int tl = c*LC + t_l;
            int tg = dir ? (SEQ-1-tl) : tl;
            size_t orow = (base + tg)*(size_t)DIN + h*HD;
            #pragma unroll
            for (int nt = 0; nt < 8; nt++){
                int p = nt*8 + pc;
                float v0 = acc[nt][hh*2+0];
                float v1 = acc[nt][hh*2+1];
                if (dir == 0){
                    v0 = fmaf(Dh, __half2float(sXt[p*72 + t_l]), v0);
                    v1 = fmaf(Dh, __half2float(sXt[(p+1)*72 + t_l]), v1);
                }
                *(float2*)(yout + orow + p) = make_float2(v0, v1);
            }
        }
    }

    // --- GEMM4: S = (W.B)^T @ X -> g_sum[p][n] (transposed store) ---
    #pragma unroll
    for (int i=0;i<8;i++){ acc[i][0]=0.f; acc[i][1]=0.f; acc[i][2]=0.f; acc[i][3]=0.f; }
    gemm64(uBwT, uXt, wm0, aoff, boff, acc);
    {
        const size_t blk = ((size_t)(dir*NH + h)*BATCH + b)*NCHK + c;
        float* dst = g_sum + blk*(HD*DS);
        const int nr = wm0 + (lane >> 2);
        const int pc = (lane & 3) * 2;
        #pragma unroll
        for (int hh = 0; hh < 2; hh++){
            int n_l = nr + hh*8;
            #pragma unroll
            for (int nt = 0; nt < 8; nt++){
                int p = nt*8 + pc;
                dst[(size_t)p*DS + n_l]     = acc[nt][hh*2+0];
                dst[(size_t)(p+1)*DS + n_l] = acc[nt][hh*2+1];
            }
        }
        if (tid == 0) g_pa[blk] = Pss[63];
    }
}

// ===================== SSD stage 2: sequential chunk-state combine ===============
__global__ void __launch_bounds__(128) ssd2_kernel(){
    const int dir = blockIdx.x;
    const int h   = blockIdx.y;
    const int b   = blockIdx.z;
    const int tid = threadIdx.x;
    const size_t blk0 = ((size_t)(dir*NH + h)*BATCH + b)*NCHK;
    float4* base = (float4*)(g_sum + blk0*(HD*DS));
    const int stride4 = HD*DS/4;
    float4 G[8];
    #pragma unroll
    for (int j=0;j<8;j++) G[j] = base[tid + j*128];
    for (int c = 1; c < NCHK; c++){
        float pa = g_pa[blk0 + c];
        float4* cur = base + (size_t)c*stride4;
        #pragma unroll
        for (int j=0;j<8;j++){
            float4 S = cur[tid + j*128];
            S.x = fmaf(pa, G[j].x, S.x);
            S.y = fmaf(pa, G[j].y, S.y);
            S.z = fmaf(pa, G[j].z, S.z);
            S.w = fmaf(pa, G[j].w, S.w);
            cur[tid + j*128] = S;
            G[j] = S;
        }
    }
}

// ===================== SSD stage 3: fixup Y += diag(P) C @ H_prev ================
// grid (2*(NCHK-1), NH, BATCH), 128 threads.
__global__ void __launch_bounds__(128) ssd3_kernel(const float* __restrict__ dtb,
                                                   const float* __restrict__ A_log,
                                                   float* __restrict__ yf,
                                                   float* __restrict__ yb){
    __shared__ __half sC[64*72];
    __shared__ __half sH[64*72];   // [p][n]
    __shared__ float Dss[64], Pss[64];
    __shared__ float w0tot;

    const int dir = blockIdx.x & 1;
    const int c   = 1 + (blockIdx.x >> 1);
    const int h   = blockIdx.y;
    const int b   = blockIdx.z;
    const int tid = threadIdx.x;
    const int lane = tid & 31, wid = tid >> 5;
    const float Ah = -expf(A_log[h]);
    const size_t base = (size_t)b*SEQ;
    float* yout = dir ? yb : yf;

    const uint32_t aoff = (uint32_t)((lane & 15) * LDSB + (lane >> 4) * 16);
    const uint32_t boff = (uint32_t)(((lane & 7) + ((lane & 16) >> 1)) * LDSB + (lane & 8) * 2);
    const uint32_t uC = smem_to_u32(sC);
    const uint32_t uH = smem_to_u32(sH);

    // dt cumsum -> P_t
    if (wid < 2){
        int i = wid*32 + lane;
        int tl = c*LC + i;
        int t = dir ? (SEQ-1-tl) : tl;
        float d = dtb[(base + t)*NH + h];
        float s = d;
        #pragma unroll
        for (int o=1;o<32;o<<=1){
            float v = __shfl_up_sync(0xffffffffu, s, o);
            if (lane >= o) s += v;
        }
        Dss[i] = s;
        if (wid == 0 && lane == 31) w0tot = s;
    }
    __syncthreads();
    if (wid < 2){
        int i = wid*32 + lane;
        float s = Dss[i] + (wid ? w0tot : 0.f);
        Pss[i] = __expf(Ah * s);
    }

    // load C (natural) and H_prev (natural [p][n])
    const size_t blkp = (((size_t)(dir*NH + h)*BATCH + b)*NCHK + (c-1))*(size_t)(HD*DS);
    for (int idx = tid; idx < 64*16; idx += 128){
        int r = idx >> 4, q = idx & 15;
        int tl = c*LC + r;
        int tg = dir ? (SEQ-1-tl) : tl;
        const float* srcC = g_xbc + (base + tg)*(size_t)CONVD + DIN + DS;
        float4 cv = *(const float4*)(srcC + q*4);
        __half2 h0, h1;
        h0.x=__float2half(cv.x); h0.y=__float2half(cv.y);
        h1.x=__float2half(cv.z); h1.y=__float2half(cv.w);
        *(__half2*)(sC + r*72 + q*4)     = h0;
        *(__half2*)(sC + r*72 + q*4 + 2) = h1;
        float4 hv = *(const float4*)(g_sum + blkp + (size_t)r*DS + q*4);
        __half2 g0, g1;
        g0.x=__float2half(hv.x); g0.y=__float2half(hv.y);
        g1.x=__float2half(hv.z); g1.y=__float2half(hv.w);
        *(__half2*)(sH + r*72 + q*4)     = g0;
        *(__half2*)(sH + r*72 + q*4 + 2) = g1;
    }
    __syncthreads();

    const int wm0 = wid * 16;
    float acc[8][4];
    #pragma unroll
    for (int i=0;i<8;i++){ acc[i][0]=0.f; acc[i][1]=0.f; acc[i][2]=0.f; acc[i][3]=0.f; }
    gemm64(uC, uH, wm0, aoff, boff, acc);   // acc[t][p] = C_t . H[:,p] over n

    {
        const int tr = wm0 + (lane >> 2);
        const int pc = (lane & 3) * 2;
        #pragma unroll
        for (int hh = 0; hh < 2; hh++){
            int t_l = tr + hh*8;
            float P = Pss[t_l];
            int tl = c*LC + t_l;
            int tg = dir ? (SEQ-1-tl) : tl;
            size_t orow = (base + tg)*(size_t)DIN + h*HD;
            #pragma unroll
            for (int nt = 0; nt < 8; nt++){
                int p = nt*8 + pc;
                float2 old = *(const float2*)(yout + orow + p);
                old.x = fmaf(P, acc[nt][hh*2+0], old.x);
                old.y = fmaf(P, acc[nt][hh*2+1], old.y);
                *(float2*)(yout + orow + p) = old;
            }
        }
    }
}

// ===================== y2 = rmsnorm((yf+yb) * silu(z)) * norm_w -> fp16 ==========
__global__ void __launch_bounds__(256) gatednorm_kernel(const float* __restrict__ z,
                                                        const float* __restrict__ w,
                                                        __half* __restrict__ y2){
    int row = blockIdx.x; int t = threadIdx.x;
    float4 ya = ((const float4*)(g_yf + (size_t)row*DIN))[t];
    float4 ybv = ((const float4*)(g_yb + (size_t)row*DIN))[t];
    float4 zv = ((const float4*)(z    + (size_t)row*DIN))[t];
    float4 v;
    v.x = (ya.x + ybv.x) * siluf(zv.x);
    v.y = (ya.y + ybv.y) * siluf(zv.y);
    v.z = (ya.z + ybv.z) * siluf(zv.z);
    v.w = (ya.w + ybv.w) * siluf(zv.w);
    float ss = v.x*v.x + v.y*v.y + v.z*v.z + v.w*v.w;
    __shared__ float sh[8];
    #pragma unroll
    for (int o=16;o;o>>=1) ss += __shfl_xor_sync(0xffffffffu, ss, o);
    if ((t&31)==0) sh[t>>5] = ss;
    __syncthreads();
    float tot = sh[0]+sh[1]+sh[2]+sh[3]+sh[4]+sh[5]+sh[6]+sh[7];
    float inv = rsqrtf(tot*(1.f/DIN) + EPSR);
    float4 wv = ((const float4*)w)[t];
    __half2 p0, p1;
    p0.x = __float2half(v.x*inv*wv.x); p0.y = __float2half(v.y*inv*wv.y);
    p1.x = __float2half(v.z*inv*wv.z); p1.y = __float2half(v.w*inv*wv.w);
    size_t o = (size_t)row*DIN + t*4;
    *(__half2*)(y2+o)   = p0;
    *(__half2*)(y2+o+2) = p1;
}

// ===================== h = rmsnorm(2*m) -> fp16 =====================
__global__ void __launch_bounds__(128) postnorm_kernel(const float* __restrict__ m,
                                                       __half* __restrict__ hbuf){
    int row = blockIdx.x; int t = threadIdx.x;
    float4 mv = ((const float4*)(m + (size_t)row*DM))[t];
    float4 v = make_float4(2.f*mv.x, 2.f*mv.y, 2.f*mv.z, 2.f*mv.w);
    float ss = v.x*v.x + v.y*v.y + v.z*v.z + v.w*v.w;
    __shared__ float sh[4];
    #pragma unroll
    for (int o=16;o;o>>=1) ss += __shfl_xor_sync(0xffffffffu, ss, o);
    if ((t&31)==0) sh[t>>5] = ss;
    __syncthreads();
    float inv = rsqrtf((sh[0]+sh[1]+sh[2]+sh[3])*(1.f/DM) + EPSR);
    __half2 p0, p1;
    p0.x = __float2half(v.x*inv); p0.y = __float2half(v.y*inv);
    p1.x = __float2half(v.z*inv); p1.y = __float2half(v.w*inv);
    size_t o = (size_t)row*DM + t*4;
    *(__half2*)(hbuf+o)   = p0;
    *(__half2*)(hbuf+o+2) = p1;
}

extern "C" void kernel_launch(void* const* d_in, const int* in_sizes, int n_in,
                              void* d_out, int out_size){
    const float* x      = (const float*)d_in[0];
    const float* mask   = (const float*)d_in[1];
    const float* W_in   = (const float*)d_in[2];
    const float* conv_w = (const float*)d_in[3];
    const float* conv_b = (const float*)d_in[4];
    const float* dt_bias= (const float*)d_in[5];
    const float* A_log  = (const float*)d_in[6];
    const float* Dv     = (const float*)d_in[7];
    const float* norm_w = (const float*)d_in[8];
    const float* W_out  = (const float*)d_in[9];
    const float* W1     = (const float*)d_in[10];
    const float* b1     = (const float*)d_in[11];
    const float* W2     = (const float*)d_in[12];
    const float* b2     = (const float*)d_in[13];

    float* out_x  = (float*)d_out;
    float* out_m  = out_x  + (size_t)NBL*DM;
    float* out_dt = out_m  + (size_t)NBL*DM;
    float* out_z  = out_dt + (size_t)NBL*NH;

    float *pxraw, *pyf, *pyb;
    __half *pu, *py2, *ph, *pff, *pwi, *pwo, *pw1, *pw2;
    cudaGetSymbolAddress((void**)&pxraw, g_xraw);
    cudaGetSymbolAddress((void**)&pyf, g_yf); cudaGetSymbolAddress((void**)&pyb, g_yb);
    cudaGetSymbolAddress((void**)&pu,  g_u);  cudaGetSymbolAddress((void**)&py2, g_y2);
    cudaGetSymbolAddress((void**)&ph,  g_h);  cudaGetSymbolAddress((void**)&pff, g_ff);
    cudaGetSymbolAddress((void**)&pwi, g_wi); cudaGetSymbolAddress((void**)&pwo, g_wo);
    cudaGetSymbolAddress((void**)&pw1, g_w1); cudaGetSymbolAddress((void**)&pw2, g_w2);

    cudaFuncSetAttribute(mma_gemm<0>, cudaFuncAttributeMaxDynamicSharedMemorySize, GSMEM_BYTES);
    cudaFuncSetAttribute(mma_gemm<1>, cudaFuncAttributeMaxDynamicSharedMemorySize, GSMEM_BYTES);
    cudaFuncSetAttribute(mma_gemm<2>, cudaFuncAttributeMaxDynamicSharedMemorySize, GSMEM_BYTES);
    cudaFuncSetAttribute(mma_gemm<3>, cudaFuncAttributeMaxDynamicSharedMemorySize, GSMEM_BYTES);

    dim3 wb(32,8);
    // 1) W_in transpose
    wconv_kernel<<<dim3((DPROJ+31)/32, DM/32),  wb>>>(W_in,  pwi, DM,  DPROJ);
    // 2) pre-norm -> fp16
    prenorm_kernel<<<NBL,128>>>(x, mask, pu);
    // 3) in-projection (fused: z, xBC, dt)
    mma_gemm<3><<<dim3((DPROJ+127)/128, NBL/128), 256, GSMEM_BYTES>>>(
        pu, pwi, DPROJ, DM, nullptr, nullptr, nullptr, nullptr,
        out_z, pxraw, out_dt, dt_bias);
    // 4) conv + silu + mask
    conv_kernel<<<(int)(((long)NBL*(CONVD/4) + 255)/256), 256>>>(conv_w, conv_b, mask);
    // 5) SSD stage 1: per-chunk tensor-core scan
    ssd1_kernel<<<dim3(2*NCHK, NH, BATCH), 128>>>(out_dt, A_log, Dv, pyf, pyb);
    // 6) SSD stage 2: sequential chunk combine
    ssd2_kernel<<<dim3(2, NH, BATCH), 128>>>();
    // 7) SSD stage 3: inter-chunk fixup
    ssd3_kernel<<<dim3(2*(NCHK-1), NH, BATCH), 128>>>(out_dt, A_log, pyf, pyb);
    // 8) W_out transpose
    wconv_kernel<<<dim3((DM+31)/32,    DIN/32), wb>>>(W_out, pwo, DIN, DM);
    // 9) gated rmsnorm -> fp16
    gatednorm_kernel<<<NBL,256>>>(out_z, norm_w, py2);
    // 10) out projection -> m
    mma_gemm<0><<<dim3(DM/128, NBL/128), 256, GSMEM_BYTES>>>(
        py2, pwo, DM, DIN, out_m, nullptr, nullptr, nullptr,
        nullptr, nullptr, nullptr, nullptr);
    // 11) h = rmsnorm(2m) -> fp16
    postnorm_kernel<<<NBL,128>>>(out_m, ph);
    // 12) W1 transpose
    wconv_kernel<<<dim3((DFF+31)/32,   DM/32),  wb>>>(W1,    pw1, DM,  DFF);
    // 13) FFN up: gelu -> fp16
    mma_gemm<1><<<dim3(DFF/128, NBL/128), 256, GSMEM_BYTES>>>(
        ph, pw1, DFF, DM, nullptr, b1, nullptr, pff,
        nullptr, nullptr, nullptr, nullptr);
    // 14) W2 transpose
    wconv_kernel<<<dim3((DM+31)/32,    DFF/32), wb>>>(W2,    pw2, DFF, DM);
    // 15) FFN down + residual
    mma_gemm<2><<<dim3(DM/128, NBL/128), 256, GSMEM_BYTES>>>(
        pff, pw2, DM, DFF, out_x, b2, out_m, nullptr,
        nullptr, nullptr, nullptr, nullptr);
}